// round 17
// baseline (speedup 1.0000x reference)
#include <cuda_runtime.h>

// GaussianBlur2D: circular Gaussian blur, separable, FUSED single kernel.
// x: [8,1,2048,2048] fp32, sigma_: scalar fp32. Reference fixes sigma=2.0.
//
// R17: sigma-specialized FAST kernel using scalar FFMA with IMMEDIATE
// weights (rt_SMSP=1, no weight regs, no pack movs) -> ~36 regs/thread ->
// __launch_bounds__(512,3) -> 48 warps/SM (vs 32 at the fma2/64-reg
// plateau). Weights hardcoded for sigma=2.0 (double-precision eval of the
// same truncated-renormalized R=8 kernel; measured rel_err 5.5e-5).
// A generic runtime-sigma kernel (R13 structure, fma.rn.f32x2) provides the
// correct fallback: the two kernels early-exit on complementary predicates.

#define HDIM   2048
#define WDIM   2048
#define RAD    8
#define TILE   128                    // output tile (both dims)
#define HALF   64                     // per-pipeline x-width
#define SROWS  (TILE + 2 * RAD)       // 144 smem rows (H results incl halo)
#define HWIN   (8 + 2 * RAD)          // 24-elem H window feeds 8 outputs
#define VWIN   (8 + 2 * RAD)          // 24-row V window feeds 8 outputs
#define HBUF   (SROWS * HALF)         // floats per half-buffer
#define SMEM_BYTES (2 * HBUF * 4)     // 72 KB

typedef unsigned long long u64;

// ---- normalized 1D weights for sigma = 2.0, R = 8 (compile-time) ----------
// w[d] = exp(-d^2/8) / (1 + 2*sum_{1..8} exp(-d^2/8)); sum = 5.01316838
__device__ __forceinline__ constexpr float wnc(int d) {
    return d == 0 ? 0.19947466f
         : d == 1 ? 0.17603573f
         : d == 2 ? 0.12098749f
         : d == 3 ? 0.06475993f
         : d == 4 ? 0.02699596f
         : d == 5 ? 0.00876431f
         : d == 6 ? 0.00221596f
         : d == 7 ? 0.00043635f
         :          0.00006692f;
}

// ---- packed f32x2 helpers (generic fallback path) --------------------------
__device__ __forceinline__ u64 pack2(float lo, float hi) {
    u64 r; asm("mov.b64 %0, {%1, %2};" : "=l"(r) : "f"(lo), "f"(hi)); return r;
}
__device__ __forceinline__ void unpack2(u64 v, float& lo, float& hi) {
    asm("mov.b64 {%0, %1}, %2;" : "=f"(lo), "=f"(hi) : "l"(v));
}
__device__ __forceinline__ u64 fma2(u64 a, u64 b, u64 c) {
    u64 r; asm("fma.rn.f32x2 %0, %1, %2, %3;" : "=l"(r) : "l"(a), "l"(b), "l"(c));
    return r;
}

// ===========================================================================
// FAST PATH (sigma == 2.0): scalar FFMA-imm
// ===========================================================================

// One H task: 2 rows x 8 cols of one 64-col half. 12 LDG.128, 272 FFMA-imm,
// 2 STS.128 pairs. t in [0,576): cg = t&7, pr = t>>3 (0..71).
template <bool W>
__device__ __forceinline__ void h_task_s(
    const float* __restrict__ src, float* __restrict__ shh,
    int xbase, int y0, int t)
{
    const int cg = t & 7;
    const int pr = t >> 3;
    const int rA = 2 * pr;
    const int rB = rA + 1;
    int gA = y0 - RAD + rA;
    int gB = gA + 1;
    if (W) { gA &= (HDIM - 1); gB &= (HDIM - 1); }
    const float* __restrict__ rowA = src + (size_t)gA * WDIM;
    const float* __restrict__ rowB = src + (size_t)gB * WDIM;
    const int c0 = cg * 8;                    // local col within half
    const int base = xbase + c0 - RAD;        // 4-aligned (RAD%4==0)

    float accA[8], accB[8];
    #pragma unroll
    for (int k = 0; k < 8; k++) { accA[k] = 0.0f; accB[k] = 0.0f; }

    #pragma unroll
    for (int g = 0; g < HWIN / 4; g++) {
        int idx = base + 4 * g;
        if (W) idx &= (WDIM - 1);             // groups never straddle the wrap
        float4 a = *reinterpret_cast<const float4*>(rowA + idx);
        float4 b = *reinterpret_cast<const float4*>(rowB + idx);
        const float ae[4] = {a.x, a.y, a.z, a.w};
        const float be[4] = {b.x, b.y, b.z, b.w};
        #pragma unroll
        for (int e = 0; e < 4; e++) {
            const int j = 4 * g + e;          // window pos 0..23
            #pragma unroll
            for (int k = 0; k < 8; k++) {     // output k uses win[k..k+2R]
                const int d = j - RAD - k;    // compile-time
                if (d < -RAD || d > RAD) continue;
                const float wd = wnc(d < 0 ? -d : d);   // immediate
                accA[k] = fmaf(wd, ae[e], accA[k]);
                accB[k] = fmaf(wd, be[e], accB[k]);
            }
        }
    }

    float4* sA = reinterpret_cast<float4*>(shh + rA * HALF + c0);
    float4* sB = reinterpret_cast<float4*>(shh + rB * HALF + c0);
    sA[0] = make_float4(accA[0], accA[1], accA[2], accA[3]);
    sA[1] = make_float4(accA[4], accA[5], accA[6], accA[7]);
    sB[0] = make_float4(accB[0], accB[1], accB[2], accB[3]);
    sB[1] = make_float4(accB[4], accB[5], accB[6], accB[7]);
}

// One V task: 1 adjacent col-pair x 8 output rows. 24 LDS.64 (float2,
// conflict-free: warp = contiguous 256B row), 272 FFMA-imm, 8 STG.64.
// t in [0,512): cp = t&31, yg = t>>5 (0..15).
__device__ __forceinline__ void v_task_s(
    const float* __restrict__ shh, float* __restrict__ dst,
    int xbase, int y0, int t)
{
    const int cp    = t & 31;
    const int yg    = t >> 5;
    const int c     = 2 * cp;
    const int ybase = 8 * yg;

    float accA[8], accB[8];
    #pragma unroll
    for (int k = 0; k < 8; k++) { accA[k] = 0.0f; accB[k] = 0.0f; }

    #pragma unroll
    for (int i = 0; i < VWIN; i++) {          // smem rows ybase .. ybase+23
        float2 v = *reinterpret_cast<const float2*>(shh + (ybase + i) * HALF + c);
        #pragma unroll
        for (int k = 0; k < 8; k++) {
            const int d = i - RAD - k;        // compile-time
            if (d < -RAD || d > RAD) continue;
            const float wd = wnc(d < 0 ? -d : d);       // immediate
            accA[k] = fmaf(wd, v.x, accA[k]);
            accB[k] = fmaf(wd, v.y, accB[k]);
        }
    }

    #pragma unroll
    for (int k = 0; k < 8; k++) {
        float2 o; o.x = accA[k]; o.y = accB[k];
        *reinterpret_cast<float2*>(dst + (size_t)(y0 + ybase + k) * WDIM
                                       + xbase + c) = o;
    }
}

template <bool W>
__device__ __forceinline__ void gb_body_s(
    const float* __restrict__ src, float* __restrict__ dst,
    float* __restrict__ shh, int xbase, int y0, int ltid, int barid)
{
    // H: 576 tasks (72 row-pairs x 8 col-groups) over 256 threads.
    h_task_s<W>(src, shh, xbase, y0, ltid);
    h_task_s<W>(src, shh, xbase, y0, ltid + 256);
    if (ltid < 64) h_task_s<W>(src, shh, xbase, y0, ltid + 512);

    asm volatile("bar.sync %0, 256;" :: "r"(barid) : "memory");

    // V: 512 tasks over 256 threads.
    v_task_s(shh, dst, xbase, y0, ltid);
    v_task_s(shh, dst, xbase, y0, ltid + 256);
}

// Fast kernel: 512 threads, 72 KB smem, forced 3 CTAs/SM (48 warps).
__global__ __launch_bounds__(512, 3) void gb_fast_kernel(
    const float* __restrict__ x, const float* __restrict__ sigma_,
    float* __restrict__ out)
{
    if (__ldg(sigma_) != 2.0f) return;        // generic kernel handles it

    extern __shared__ float sh[];             // [2][SROWS*HALF]
    const int tid  = threadIdx.x;
    const int half = tid >> 8;                // 0 or 1 (warp-uniform)
    const int ltid = tid & 255;

    const int x0 = blockIdx.x * TILE;
    const int y0 = blockIdx.y * TILE;
    const int xbase = x0 + half * HALF;
    const float* __restrict__ src = x   + (size_t)blockIdx.z * HDIM * WDIM;
    float*       __restrict__ dst = out + (size_t)blockIdx.z * HDIM * WDIM;
    float* __restrict__ shh = sh + half * HBUF;

    const bool wrap = (blockIdx.x == 0) | (blockIdx.x == (WDIM / TILE - 1)) |
                      (blockIdx.y == 0) | (blockIdx.y == (HDIM / TILE - 1));
    if (!wrap) gb_body_s<false>(src, dst, shh, xbase, y0, ltid, 1 + half);
    else       gb_body_s<true >(src, dst, shh, xbase, y0, ltid, 1 + half);
}

// ===========================================================================
// GENERIC PATH (any sigma): R13 structure, runtime weights, fma.rn.f32x2
// ===========================================================================

template <bool W>
__device__ __forceinline__ void h_task_g(
    const float* __restrict__ src, float* __restrict__ shh,
    const u64* __restrict__ wn2, int xbase, int y0, int t)
{
    const int cg = t & 7;
    const int pr = t >> 3;
    const int rA = 2 * pr;
    const int rB = rA + 1;
    int gA = y0 - RAD + rA;
    int gB = gA + 1;
    if (W) { gA &= (HDIM - 1); gB &= (HDIM - 1); }
    const float* __restrict__ rowA = src + (size_t)gA * WDIM;
    const float* __restrict__ rowB = src + (size_t)gB * WDIM;
    const int c0 = cg * 8;
    const int base = xbase + c0 - RAD;

    u64 acc[8];
    #pragma unroll
    for (int k = 0; k < 8; k++) acc[k] = 0ull;

    #pragma unroll
    for (int g = 0; g < HWIN / 4; g++) {
        int idx = base + 4 * g;
        if (W) idx &= (WDIM - 1);
        float4 a = *reinterpret_cast<const float4*>(rowA + idx);
        float4 b = *reinterpret_cast<const float4*>(rowB + idx);
        const float ae[4] = {a.x, a.y, a.z, a.w};
        const float be[4] = {b.x, b.y, b.z, b.w};
        #pragma unroll
        for (int e = 0; e < 4; e++) {
            const int j = 4 * g + e;
            u64 v = pack2(ae[e], be[e]);
            #pragma unroll
            for (int k = 0; k < 8; k++) {
                const int d = j - RAD - k;
                if (d < -RAD || d > RAD) continue;
                const int ad = d < 0 ? -d : d;
                acc[k] = fma2(wn2[ad], v, acc[k]);
            }
        }
    }

    float la[8], lb[8];
    #pragma unroll
    for (int k = 0; k < 8; k++) unpack2(acc[k], la[k], lb[k]);
    float4* sA = reinterpret_cast<float4*>(shh + rA * HALF + c0);
    float4* sB = reinterpret_cast<float4*>(shh + rB * HALF + c0);
    sA[0] = make_float4(la[0], la[1], la[2], la[3]);
    sA[1] = make_float4(la[4], la[5], la[6], la[7]);
    sB[0] = make_float4(lb[0], lb[1], lb[2], lb[3]);
    sB[1] = make_float4(lb[4], lb[5], lb[6], lb[7]);
}

__device__ __forceinline__ void v_task_g(
    const float* __restrict__ shh, float* __restrict__ dst,
    const u64* __restrict__ wn2, int xbase, int y0, int t)
{
    const int cp    = t & 31;
    const int yg    = t >> 5;
    const int c     = 2 * cp;
    const int ybase = 8 * yg;

    u64 acc[8];
    #pragma unroll
    for (int k = 0; k < 8; k++) acc[k] = 0ull;

    #pragma unroll
    for (int i = 0; i < VWIN; i++) {
        u64 v = *reinterpret_cast<const u64*>(shh + (ybase + i) * HALF + c);
        #pragma unroll
        for (int k = 0; k < 8; k++) {
            const int d = i - RAD - k;
            if (d < -RAD || d > RAD) continue;
            const int ad = d < 0 ? -d : d;
            acc[k] = fma2(wn2[ad], v, acc[k]);
        }
    }

    #pragma unroll
    for (int k = 0; k < 8; k++)
        *reinterpret_cast<u64*>(dst + (size_t)(y0 + ybase + k) * WDIM
                                    + xbase + c) = acc[k];
}

__global__ __launch_bounds__(512, 2) void gb_generic_kernel(
    const float* __restrict__ x, const float* __restrict__ sigma_,
    float* __restrict__ out)
{
    if (__ldg(sigma_) == 2.0f) return;        // fast kernel already did it

    extern __shared__ float sh[];
    const int tid  = threadIdx.x;
    const int half = tid >> 8;
    const int ltid = tid & 255;

    const int x0 = blockIdx.x * TILE;
    const int y0 = blockIdx.y * TILE;
    const int xbase = x0 + half * HALF;
    const float* __restrict__ src = x   + (size_t)blockIdx.z * HDIM * WDIM;
    float*       __restrict__ dst = out + (size_t)blockIdx.z * HDIM * WDIM;
    float* __restrict__ shh = sh + half * HBUF;

    u64 wn2[RAD + 1];
    {
        float s = fmaxf(sigma_[0], 0.0f) + 1e-6f;
        float inv2s2 = 1.0f / (2.0f * s * s);
        float w[RAD + 1];
        float sum = 0.0f;
        #pragma unroll
        for (int d = 0; d <= RAD; d++) {
            w[d] = expf(-(float)(d * d) * inv2s2);
            sum += (d == 0) ? w[d] : 2.0f * w[d];
        }
        float inv = 1.0f / sum;
        #pragma unroll
        for (int d = 0; d <= RAD; d++) {
            float wd = w[d] * inv;
            wn2[d] = pack2(wd, wd);
        }
    }

    const bool wrap = (blockIdx.x == 0) | (blockIdx.x == (WDIM / TILE - 1)) |
                      (blockIdx.y == 0) | (blockIdx.y == (HDIM / TILE - 1));
    const int barid = 1 + half;
    if (!wrap) {
        h_task_g<false>(src, shh, wn2, xbase, y0, ltid);
        h_task_g<false>(src, shh, wn2, xbase, y0, ltid + 256);
        if (ltid < 64) h_task_g<false>(src, shh, wn2, xbase, y0, ltid + 512);
        asm volatile("bar.sync %0, 256;" :: "r"(barid) : "memory");
        v_task_g(shh, dst, wn2, xbase, y0, ltid);
        v_task_g(shh, dst, wn2, xbase, y0, ltid + 256);
    } else {
        h_task_g<true>(src, shh, wn2, xbase, y0, ltid);
        h_task_g<true>(src, shh, wn2, xbase, y0, ltid + 256);
        if (ltid < 64) h_task_g<true>(src, shh, wn2, xbase, y0, ltid + 512);
        asm volatile("bar.sync %0, 256;" :: "r"(barid) : "memory");
        v_task_g(shh, dst, wn2, xbase, y0, ltid);
        v_task_g(shh, dst, wn2, xbase, y0, ltid + 256);
    }
}

// ---------------------------------------------------------------------------
extern "C" void kernel_launch(void* const* d_in, const int* in_sizes, int n_in,
                              void* d_out, int out_size)
{
    const float* x      = (const float*)d_in[0];
    const float* sigma_ = (const float*)d_in[1];
    float* out          = (float*)d_out;

    // idempotent; no allocation; capture-safe (host-side attribute set)
    cudaFuncSetAttribute(gb_fast_kernel,
                         cudaFuncAttributeMaxDynamicSharedMemorySize,
                         SMEM_BYTES);
    cudaFuncSetAttribute(gb_generic_kernel,
                         cudaFuncAttributeMaxDynamicSharedMemorySize,
                         SMEM_BYTES);

    dim3 grid(WDIM / TILE, HDIM / TILE, 8);   // 16 x 16 x 8 = 2048 CTAs
    gb_fast_kernel   <<<grid, 512, SMEM_BYTES>>>(x, sigma_, out);
    gb_generic_kernel<<<grid, 512, SMEM_BYTES>>>(x, sigma_, out);
}